// round 8
// baseline (speedup 1.0000x reference)
#include <cuda_runtime.h>

#define BB 8
#define TT 1024
#define DD 1024
#define FF 4096
#define MM (BB*TT)          // 8192 rows
#define D4 (DD/4)

// ---------------- scratch (static device allocations; allowed) ----------------
__device__ float g_xn [MM*DD];
__device__ float g_mk [MM*DD];
__device__ float g_mv [MM*DD];
__device__ float g_mr [MM*DD];
__device__ float g_k  [MM*DD];
__device__ float g_v  [MM*DD];
__device__ float g_r  [MM*DD];
__device__ float g_rw [MM*DD];   // r * wkv
__device__ float g_x1 [MM*DD];
__device__ float g_xn2[MM*DD];
__device__ float g_mck[MM*DD];
__device__ float g_mcr[MM*DD];
__device__ float g_kc [MM*FF];   // relu(.)^2 of channel-mix key
__device__ float g_rc [MM*DD];

// ---------------- LayerNorm: one block per row, D=1024, 256 threads ----------------
__global__ void __launch_bounds__(256) ln_kernel(
    const float* __restrict__ x, const float* __restrict__ g,
    const float* __restrict__ b, float* __restrict__ y,
    float* __restrict__ last)
{
    const int row = blockIdx.x;
    const float4* xr = (const float4*)(x + (size_t)row * DD);
    float4 v = xr[threadIdx.x];
    float s  = v.x + v.y + v.z + v.w;
    float ss = v.x*v.x + v.y*v.y + v.z*v.z + v.w*v.w;
#pragma unroll
    for (int o = 16; o; o >>= 1) {
        s  += __shfl_xor_sync(0xffffffffu, s,  o);
        ss += __shfl_xor_sync(0xffffffffu, ss, o);
    }
    __shared__ float sh[16];
    const int w = threadIdx.x >> 5, l = threadIdx.x & 31;
    if (l == 0) { sh[w] = s; sh[8 + w] = ss; }
    __syncthreads();
    s = 0.f; ss = 0.f;
#pragma unroll
    for (int i = 0; i < 8; i++) { s += sh[i]; ss += sh[8 + i]; }
    const float mean = s * (1.0f / DD);
    const float var  = ss * (1.0f / DD) - mean * mean;
    const float rstd = rsqrtf(var + 1e-3f);

    float4 gg = ((const float4*)g)[threadIdx.x];
    float4 bb = ((const float4*)b)[threadIdx.x];
    float4 o;
    o.x = (v.x - mean) * rstd * gg.x + bb.x;
    o.y = (v.y - mean) * rstd * gg.y + bb.y;
    o.z = (v.z - mean) * rstd * gg.z + bb.z;
    o.w = (v.w - mean) * rstd * gg.w + bb.w;
    ((float4*)(y + (size_t)row * DD))[threadIdx.x] = o;
    if (last && (row % TT) == (TT - 1)) {
        ((float4*)(last + (size_t)(row / TT) * DD))[threadIdx.x] = o;
    }
}

// ---------------- token-shift + lerp mixing (2 or 3 outputs) ----------------
template<int NOUT>
__global__ void __launch_bounds__(256) mix_kernel(
    const float* __restrict__ xn, const float* __restrict__ x0,
    const float* __restrict__ m0, const float* __restrict__ m1, const float* __restrict__ m2,
    float* __restrict__ o0, float* __restrict__ o1, float* __restrict__ o2)
{
    const int i4 = blockIdx.x * blockDim.x + threadIdx.x;
    if (i4 >= MM * D4) return;
    const int d4 = i4 % D4;
    const int bt = i4 / D4;
    const int t = bt % TT, b = bt / TT;
    float4 xc = ((const float4*)xn)[i4];
    float4 xp = (t == 0) ? ((const float4*)x0)[b * D4 + d4]
                         : ((const float4*)xn)[i4 - D4];
    {
        float4 m = ((const float4*)m0)[d4];
        float4 o;
        o.x = xp.x + (xc.x - xp.x) * m.x;
        o.y = xp.y + (xc.y - xp.y) * m.y;
        o.z = xp.z + (xc.z - xp.z) * m.z;
        o.w = xp.w + (xc.w - xp.w) * m.w;
        ((float4*)o0)[i4] = o;
    }
    if (NOUT >= 2) {
        float4 m = ((const float4*)m1)[d4];
        float4 o;
        o.x = xp.x + (xc.x - xp.x) * m.x;
        o.y = xp.y + (xc.y - xp.y) * m.y;
        o.z = xp.z + (xc.z - xp.z) * m.z;
        o.w = xp.w + (xc.w - xp.w) * m.w;
        ((float4*)o1)[i4] = o;
    }
    if (NOUT >= 3) {
        float4 m = ((const float4*)m2)[d4];
        float4 o;
        o.x = xp.x + (xc.x - xp.x) * m.x;
        o.y = xp.y + (xc.y - xp.y) * m.y;
        o.z = xp.z + (xc.z - xp.z) * m.z;
        o.w = xp.w + (xc.w - xp.w) * m.w;
        ((float4*)o2)[i4] = o;
    }
}

// ---------------- WKV scan: 4-deep prefetch, 64-thread blocks ----------------
__global__ void __launch_bounds__(64) wkv_kernel(
    const float* __restrict__ k, const float* __restrict__ v, const float* __restrict__ r,
    const float* __restrict__ a0, const float* __restrict__ b0, const float* __restrict__ p0,
    const float* __restrict__ decay, const float* __restrict__ first,
    float* __restrict__ rw,
    float* __restrict__ aa_o, float* __restrict__ bb_o, float* __restrict__ pp_o)
{
    const int idx = blockIdx.x * blockDim.x + threadIdx.x;
    if (idx >= BB * DD) return;
    const int d = idx % DD, b = idx / DD;
    float aa = a0[idx], bb = b0[idx], pp = p0[idx];
    const float w = -expf(decay[d]);
    const float u = first[d];
    const size_t base = (size_t)b * TT * DD + d;

    float kb[4], vb[4], rb[4];
#pragma unroll
    for (int j = 0; j < 4; j++) {
        kb[j] = k[base + (size_t)j * DD];
        vb[j] = v[base + (size_t)j * DD];
        rb[j] = r[base + (size_t)j * DD];
    }

    for (int t0 = 0; t0 < TT; t0 += 4) {
        float kn[4], vn[4], rn[4];
        if (t0 + 4 < TT) {
#pragma unroll
            for (int j = 0; j < 4; j++) {
                const size_t off = base + (size_t)(t0 + 4 + j) * DD;
                kn[j] = k[off]; vn[j] = v[off]; rn[j] = r[off];
            }
        } else {
#pragma unroll
            for (int j = 0; j < 4; j++) { kn[j] = 0.f; vn[j] = 0.f; rn[j] = 0.f; }
        }
#pragma unroll
        for (int j = 0; j < 4; j++) {
            const size_t off = base + (size_t)(t0 + j) * DD;
            const float kt = kb[j], vt = vb[j], rt = rb[j];
            float ww = u + kt;
            float p  = fmaxf(pp, ww);
            float e1 = expf(pp - p), e2 = expf(ww - p);
            float wkv = (e1 * aa + e2 * vt) / (e1 * bb + e2);
            rw[off] = rt * wkv;
            float ww2 = pp + w;
            float p2  = fmaxf(ww2, kt);
            float e1b = expf(ww2 - p2), e2b = expf(kt - p2);
            aa = e1b * aa + e2b * vt;
            bb = e1b * bb + e2b;
            pp = p2;
        }
#pragma unroll
        for (int j = 0; j < 4; j++) { kb[j] = kn[j]; vb[j] = vn[j]; rb[j] = rn[j]; }
    }
    aa_o[idx] = aa; bb_o[idx] = bb; pp_o[idx] = pp;
}

// ---------------- TF32 tensor-core GEMM: 128x128x16, mma.m16n8k8 ----------------
// 3-stage fragment-permuted smem pipeline; STS for slab s+1 overlaps compute of slab s.
// EPI: 0=none, 1=sigmoid, 2=relu^2, 3=acc+X, 4=X + S*acc

__device__ __forceinline__ unsigned f2tf32(float f) {
    unsigned u;
    asm("cvt.rna.tf32.f32 %0, %1;" : "=r"(u) : "f"(f));
    return u;
}

__device__ __forceinline__ void mma_tf32(
    float& c0, float& c1, float& c2, float& c3,
    unsigned a0, unsigned a1, unsigned a2, unsigned a3,
    unsigned b0, unsigned b1)
{
    asm volatile(
        "mma.sync.aligned.m16n8k8.row.col.f32.tf32.tf32.f32 "
        "{%0,%1,%2,%3}, {%4,%5,%6,%7}, {%8,%9}, {%0,%1,%2,%3};\n"
        : "+f"(c0), "+f"(c1), "+f"(c2), "+f"(c3)
        : "r"(a0), "r"(a1), "r"(a2), "r"(a3), "r"(b0), "r"(b1));
}

template<int EPI>
__global__ void __launch_bounds__(256, 2) tgemm(
    const float* __restrict__ A, const float* __restrict__ Bm, float* __restrict__ C,
    int M, int N, int K,
    const float* __restrict__ X, const float* __restrict__ S)
{
    // Three stages: stage word-offset = stage * 2048 (8 KB each side per stage).
    __shared__ __align__(16) unsigned As[6144];   // 24 KB
    __shared__ __align__(16) unsigned Bs[6144];   // 24 KB

    const int tid  = threadIdx.x;
    const int lane = tid & 31;
    const int warp = tid >> 5;
    const int wm   = warp >> 2;     // 0..1
    const int wn   = warp & 3;      // 0..3
    const int bm   = blockIdx.y * 128;
    const int bn   = blockIdx.x * 128;

    const int ra  = tid >> 2;           // 0..63
    const int kqa = (tid & 3) << 2;     // 0,4,8,12
    int offA[2], offB[2][4];
#pragma unroll
    for (int i = 0; i < 2; i++) {
        const int m  = i * 64 + ra;
        const int r  = m & 15;
        const int mt = m >> 4;
        const int ks = kqa >> 3;            // 0 or 1
        const int ch = (kqa >> 2) & 1;      // c>>2 bit
        const int reg = (r >> 3) | (ch << 1);
        const int swz = (reg << 2) ^ (ks << 4);
        offA[i] = (((mt << 1) | ks) << 7) + (reg << 5) + ((((r & 7) << 2)) ^ swz);
        const int kB  = i * 8 + warp;       // 0..15
        const int ksB = kB >> 3;
        const int regB = (kB >> 2) & 1;
        const int nt  = lane >> 1;          // 0..15
        const int swzB = (((nt & 7) << 2)) ^ (((nt >> 3) & 1) << 1);
#pragma unroll
        for (int e = 0; e < 4; e++) {
            const int n = (lane << 2) + e;
            const int lane_s = ((n & 7) << 2) | (kB & 3);
            offB[i][e] = (((nt << 1) | ksB) << 6) + (regB << 5) + (lane_s ^ swzB);
        }
    }

    const float* Ap0 = A + (size_t)(bm + ra) * K + kqa;
    const float* Ap1 = A + (size_t)(bm + 64 + ra) * K + kqa;
    const float* Bp0 = Bm + (size_t)warp * N + bn + (lane << 2);
    const float* Bp1 = Bm + (size_t)(warp + 8) * N + bn + (lane << 2);

    float acc[4][4][4];
#pragma unroll
    for (int i = 0; i < 4; i++)
#pragma unroll
        for (int j = 0; j < 4; j++)
#pragma unroll
            for (int e = 0; e < 4; e++) acc[i][j][e] = 0.f;

    float4 avr[2], bvr[2];

    // ---- prologue: slab 0 -> stage 0; slab 1 -> regs ----
    avr[0] = *(const float4*)Ap0;
    avr[1] = *(const float4*)Ap1;
    bvr[0] = *(const float4*)Bp0;
    bvr[1] = *(const float4*)Bp1;
#pragma unroll
    for (int i = 0; i < 2; i++) {
        uint4 pa;
        pa.x = f2tf32(avr[i].x); pa.y = f2tf32(avr[i].y);
        pa.z = f2tf32(avr[i].z); pa.w = f2tf32(avr[i].w);
        *(uint4*)&As[offA[i]] = pa;
        Bs[offB[i][0]] = f2tf32(bvr[i].x);
        Bs[offB[i][1]] = f2tf32(bvr[i].y);
        Bs[offB[i][2]] = f2tf32(bvr[i].z);
        Bs[offB[i][3]] = f2tf32(bvr[i].w);
    }
    avr[0] = *(const float4*)(Ap0 + 16);
    avr[1] = *(const float4*)(Ap1 + 16);
    bvr[0] = *(const float4*)(Bp0 + (size_t)16 * N);
    bvr[1] = *(const float4*)(Bp1 + (size_t)16 * N);

    const int ns = K >> 4;
    int cst = 0;                 // compute stage for slab s
    for (int s = 0; s < ns; s++) {
        __syncthreads();         // guards: STS(slab s) done (prev iter / prologue); compute(s-2) done

        // ---- STS: regs (slab s+1) -> stage (cst+1)%3 ----
        if (s + 1 < ns) {
            const int wst = (cst == 2) ? 0 : cst + 1;
            const int wb = wst << 11;
#pragma unroll
            for (int i = 0; i < 2; i++) {
                uint4 pa;
                pa.x = f2tf32(avr[i].x); pa.y = f2tf32(avr[i].y);
                pa.z = f2tf32(avr[i].z); pa.w = f2tf32(avr[i].w);
                *(uint4*)&As[wb + offA[i]] = pa;
                Bs[wb + offB[i][0]] = f2tf32(bvr[i].x);
                Bs[wb + offB[i][1]] = f2tf32(bvr[i].y);
                Bs[wb + offB[i][2]] = f2tf32(bvr[i].z);
                Bs[wb + offB[i][3]] = f2tf32(bvr[i].w);
            }
        }
        // ---- LDG: slab s+2 -> regs ----
        if (s + 2 < ns) {
            const int k2 = (s + 2) << 4;
            avr[0] = *(const float4*)(Ap0 + k2);
            avr[1] = *(const float4*)(Ap1 + k2);
            bvr[0] = *(const float4*)(Bp0 + (size_t)k2 * N);
            bvr[1] = *(const float4*)(Bp1 + (size_t)k2 * N);
        }

        // ---- compute slab s from stage cst ----
        const unsigned* Asb = As + (cst << 11);
        const unsigned* Bsb = Bs + (cst << 11);
#pragma unroll
        for (int ks = 0; ks < 2; ks++) {
            unsigned af[4][4], bf[4][2];
#pragma unroll
            for (int mt = 0; mt < 4; mt++) {
                const int mtg = wm * 4 + mt;
                const int base = (((mtg << 1) | ks) << 7);
#pragma unroll
                for (int reg = 0; reg < 4; reg++)
                    af[mt][reg] = Asb[base + (reg << 5) + (lane ^ (reg << 2) ^ (ks << 4))];
            }
#pragma unroll
            for (int nt = 0; nt < 4; nt++) {
                const int ntg = wn * 4 + nt;
                const int swzB = (((ntg & 7) << 2)) ^ (((ntg >> 3) & 1) << 1);
                const int base = (((ntg << 1) | ks) << 6);
#pragma unroll
                for (int reg = 0; reg < 2; reg++)
                    bf[nt][reg] = Bsb[base + (reg << 5) + (lane ^ swzB)];
            }
#pragma unroll
            for (int mt = 0; mt < 4; mt++)
#pragma unroll
                for (int nt = 0; nt < 4; nt++)
                    mma_tf32(acc[mt][nt][0], acc[mt][nt][1], acc[mt][nt][2], acc[mt][nt][3],
                             af[mt][0], af[mt][1], af[mt][2], af[mt][3],
                             bf[nt][0], bf[nt][1]);
        }
        cst = (cst == 2) ? 0 : cst + 1;
    }

    // ---- epilogue ----
    const int rbase = bm + wm * 64 + (lane >> 2);
    const int cbase = bn + wn * 32 + ((lane & 3) << 1);
#pragma unroll
    for (int mt = 0; mt < 4; mt++) {
#pragma unroll
        for (int h = 0; h < 2; h++) {
            const int row = rbase + mt * 16 + h * 8;
#pragma unroll
            for (int nt = 0; nt < 4; nt++) {
                const int col = cbase + nt * 8;
                const size_t idx = (size_t)row * N + col;
                float v0 = acc[mt][nt][h * 2 + 0];
                float v1 = acc[mt][nt][h * 2 + 1];
                if (EPI == 1) {
                    v0 = 1.f / (1.f + expf(-v0));
                    v1 = 1.f / (1.f + expf(-v1));
                } else if (EPI == 2) {
                    v0 = fmaxf(v0, 0.f); v0 *= v0;
                    v1 = fmaxf(v1, 0.f); v1 *= v1;
                } else if (EPI == 3) {
                    float2 xv = *(const float2*)&X[idx];
                    v0 += xv.x; v1 += xv.y;
                } else if (EPI == 4) {
                    float2 xv = *(const float2*)&X[idx];
                    float2 sv = *(const float2*)&S[idx];
                    v0 = xv.x + sv.x * v0;
                    v1 = xv.y + sv.y * v1;
                }
                float2 o; o.x = v0; o.y = v1;
                *(float2*)&C[idx] = o;
            }
        }
    }
}

// ---------------- host ----------------
extern "C" void kernel_launch(void* const* d_in, const int* in_sizes, int n_in,
                              void* d_out, int out_size)
{
    const float* x        = (const float*)d_in[0];
    const float* att_x    = (const float*)d_in[1];
    const float* att_a    = (const float*)d_in[2];
    const float* att_b    = (const float*)d_in[3];
    const float* att_p    = (const float*)d_in[4];
    const float* ffn_x    = (const float*)d_in[5];
    const float* ln1_g    = (const float*)d_in[6];
    const float* ln1_b    = (const float*)d_in[7];
    const float* ln2_g    = (const float*)d_in[8];
    const float* ln2_b    = (const float*)d_in[9];
    const float* tm_mix_k = (const float*)d_in[10];
    const float* tm_mix_v = (const float*)d_in[11];
    const float* tm_mix_r = (const float*)d_in[12];
    const float* tm_decay = (const float*)d_in[13];
    const float* tm_first = (const float*)d_in[14];
    const float* Wk       = (const float*)d_in[15];
    const float* Wv       = (const float*)d_in[16];
    const float* Wr       = (const float*)d_in[17];
    const float* Wo       = (const float*)d_in[18];
    const float* cm_mix_k = (const float*)d_in[19];
    const float* cm_mix_r = (const float*)d_in[20];
    const float* Ck       = (const float*)d_in[21];
    const float* Cr       = (const float*)d_in[22];
    const float* Cv       = (const float*)d_in[23];

    float* out = (float*)d_out;
    const size_t OFS_XN1 = (size_t)MM * DD;
    const size_t OFS_AA  = OFS_XN1 + (size_t)BB * DD;
    const size_t OFS_BB  = OFS_AA  + (size_t)BB * DD;
    const size_t OFS_PP  = OFS_BB  + (size_t)BB * DD;
    const size_t OFS_XN2 = OFS_PP  + (size_t)BB * DD;

    float *xn, *mk, *mv, *mr, *kk, *vv, *rr, *rw, *x1, *xn2, *mck, *mcr, *kc, *rc;
    cudaGetSymbolAddress((void**)&xn,  g_xn);
    cudaGetSymbolAddress((void**)&mk,  g_mk);
    cudaGetSymbolAddress((void**)&mv,  g_mv);
    cudaGetSymbolAddress((void**)&mr,  g_mr);
    cudaGetSymbolAddress((void**)&kk,  g_k);
    cudaGetSymbolAddress((void**)&vv,  g_v);
    cudaGetSymbolAddress((void**)&rr,  g_r);
    cudaGetSymbolAddress((void**)&rw,  g_rw);
    cudaGetSymbolAddress((void**)&x1,  g_x1);
    cudaGetSymbolAddress((void**)&xn2, g_xn2);
    cudaGetSymbolAddress((void**)&mck, g_mck);
    cudaGetSymbolAddress((void**)&mcr, g_mcr);
    cudaGetSymbolAddress((void**)&kc,  g_kc);
    cudaGetSymbolAddress((void**)&rc,  g_rc);

    const int mixBlocks = (MM * D4 + 255) / 256;

    // 1) ln1(x) -> xn  (+ xn_last output)
    ln_kernel<<<MM, 256>>>(x, ln1_g, ln1_b, xn, out + OFS_XN1);

    // 2) token shift + mix for k/v/r
    mix_kernel<3><<<mixBlocks, 256>>>(xn, att_x, tm_mix_k, tm_mix_v, tm_mix_r, mk, mv, mr);

    // 3) K, V, R GEMMs (R fused sigmoid)
    dim3 gD(DD / 128, MM / 128);
    tgemm<0><<<gD, 256>>>(mk, Wk, kk, MM, DD, DD, nullptr, nullptr);
    tgemm<0><<<gD, 256>>>(mv, Wv, vv, MM, DD, DD, nullptr, nullptr);
    tgemm<1><<<gD, 256>>>(mr, Wr, rr, MM, DD, DD, nullptr, nullptr);

    // 4) WKV scan (fused r*wkv), state outputs — 64-thread blocks on 128 CTAs
    wkv_kernel<<<(BB * DD) / 64, 64>>>(kk, vv, rr, att_a, att_b, att_p,
                                       tm_decay, tm_first, rw,
                                       out + OFS_AA, out + OFS_BB, out + OFS_PP);

    // 5) x1 = x + (r*wkv) @ Wo
    tgemm<3><<<gD, 256>>>(rw, Wo, x1, MM, DD, DD, x, nullptr);

    // 6) ln2(x1) -> xn2 (+ xn2_last output)
    ln_kernel<<<MM, 256>>>(x1, ln2_g, ln2_b, xn2, out + OFS_XN2);

    // 7) channel-mix token shift
    mix_kernel<2><<<mixBlocks, 256>>>(xn2, ffn_x, cm_mix_k, cm_mix_r, nullptr, mck, mcr, nullptr);

    // 8) kc = relu(mck @ Ck)^2   [M=8192, N=4096, K=1024]
    dim3 gF(FF / 128, MM / 128);
    tgemm<2><<<gF, 256>>>(mck, Ck, kc, MM, FF, DD, nullptr, nullptr);

    // 9) rc = sigmoid(mcr @ Cr)
    tgemm<1><<<gD, 256>>>(mcr, Cr, rc, MM, DD, DD, nullptr, nullptr);

    // 10) out = x1 + rc * (kc @ Cv)   [M=8192, N=1024, K=4096]
    tgemm<4><<<gD, 256>>>(kc, Cv, out, MM, DD, FF, x1, rc);
}

// round 9
// speedup vs baseline: 1.2020x; 1.2020x over previous
#include <cuda_runtime.h>

#define BB 8
#define TT 1024
#define DD 1024
#define FF 4096
#define MM (BB*TT)          // 8192 rows
#define D4 (DD/4)

// ---------------- scratch (static device allocations; allowed) ----------------
__device__ float g_xn [MM*DD];
__device__ float g_mk [MM*DD];
__device__ float g_mv [MM*DD];
__device__ float g_mr [MM*DD];
__device__ float g_k  [MM*DD];
__device__ float g_v  [MM*DD];
__device__ float g_r  [MM*DD];
__device__ float g_rw [MM*DD];   // r * wkv
__device__ float g_x1 [MM*DD];
__device__ float g_xn2[MM*DD];
__device__ float g_mck[MM*DD];
__device__ float g_mcr[MM*DD];
__device__ float g_kc [MM*FF];   // relu(.)^2 of channel-mix key
__device__ float g_rc [MM*DD];

// ---------------- LayerNorm: one block per row, D=1024, 256 threads ----------------
__global__ void __launch_bounds__(256) ln_kernel(
    const float* __restrict__ x, const float* __restrict__ g,
    const float* __restrict__ b, float* __restrict__ y,
    float* __restrict__ last)
{
    const int row = blockIdx.x;
    const float4* xr = (const float4*)(x + (size_t)row * DD);
    float4 v = xr[threadIdx.x];
    float s  = v.x + v.y + v.z + v.w;
    float ss = v.x*v.x + v.y*v.y + v.z*v.z + v.w*v.w;
#pragma unroll
    for (int o = 16; o; o >>= 1) {
        s  += __shfl_xor_sync(0xffffffffu, s,  o);
        ss += __shfl_xor_sync(0xffffffffu, ss, o);
    }
    __shared__ float sh[16];
    const int w = threadIdx.x >> 5, l = threadIdx.x & 31;
    if (l == 0) { sh[w] = s; sh[8 + w] = ss; }
    __syncthreads();
    s = 0.f; ss = 0.f;
#pragma unroll
    for (int i = 0; i < 8; i++) { s += sh[i]; ss += sh[8 + i]; }
    const float mean = s * (1.0f / DD);
    const float var  = ss * (1.0f / DD) - mean * mean;
    const float rstd = rsqrtf(var + 1e-3f);

    float4 gg = ((const float4*)g)[threadIdx.x];
    float4 bb = ((const float4*)b)[threadIdx.x];
    float4 o;
    o.x = (v.x - mean) * rstd * gg.x + bb.x;
    o.y = (v.y - mean) * rstd * gg.y + bb.y;
    o.z = (v.z - mean) * rstd * gg.z + bb.z;
    o.w = (v.w - mean) * rstd * gg.w + bb.w;
    ((float4*)(y + (size_t)row * DD))[threadIdx.x] = o;
    if (last && (row % TT) == (TT - 1)) {
        ((float4*)(last + (size_t)(row / TT) * DD))[threadIdx.x] = o;
    }
}

// ---------------- token-shift + lerp mixing (2 or 3 outputs) ----------------
template<int NOUT>
__global__ void __launch_bounds__(256) mix_kernel(
    const float* __restrict__ xn, const float* __restrict__ x0,
    const float* __restrict__ m0, const float* __restrict__ m1, const float* __restrict__ m2,
    float* __restrict__ o0, float* __restrict__ o1, float* __restrict__ o2)
{
    const int i4 = blockIdx.x * blockDim.x + threadIdx.x;
    if (i4 >= MM * D4) return;
    const int d4 = i4 % D4;
    const int bt = i4 / D4;
    const int t = bt % TT, b = bt / TT;
    float4 xc = ((const float4*)xn)[i4];
    float4 xp = (t == 0) ? ((const float4*)x0)[b * D4 + d4]
                         : ((const float4*)xn)[i4 - D4];
    {
        float4 m = ((const float4*)m0)[d4];
        float4 o;
        o.x = xp.x + (xc.x - xp.x) * m.x;
        o.y = xp.y + (xc.y - xp.y) * m.y;
        o.z = xp.z + (xc.z - xp.z) * m.z;
        o.w = xp.w + (xc.w - xp.w) * m.w;
        ((float4*)o0)[i4] = o;
    }
    if (NOUT >= 2) {
        float4 m = ((const float4*)m1)[d4];
        float4 o;
        o.x = xp.x + (xc.x - xp.x) * m.x;
        o.y = xp.y + (xc.y - xp.y) * m.y;
        o.z = xp.z + (xc.z - xp.z) * m.z;
        o.w = xp.w + (xc.w - xp.w) * m.w;
        ((float4*)o1)[i4] = o;
    }
    if (NOUT >= 3) {
        float4 m = ((const float4*)m2)[d4];
        float4 o;
        o.x = xp.x + (xc.x - xp.x) * m.x;
        o.y = xp.y + (xc.y - xp.y) * m.y;
        o.z = xp.z + (xc.z - xp.z) * m.z;
        o.w = xp.w + (xc.w - xp.w) * m.w;
        ((float4*)o2)[i4] = o;
    }
}

// ---------------- WKV scan: 4-deep prefetch, 64-thread blocks ----------------
__global__ void __launch_bounds__(64) wkv_kernel(
    const float* __restrict__ k, const float* __restrict__ v, const float* __restrict__ r,
    const float* __restrict__ a0, const float* __restrict__ b0, const float* __restrict__ p0,
    const float* __restrict__ decay, const float* __restrict__ first,
    float* __restrict__ rw,
    float* __restrict__ aa_o, float* __restrict__ bb_o, float* __restrict__ pp_o)
{
    const int idx = blockIdx.x * blockDim.x + threadIdx.x;
    if (idx >= BB * DD) return;
    const int d = idx % DD, b = idx / DD;
    float aa = a0[idx], bb = b0[idx], pp = p0[idx];
    const float w = -expf(decay[d]);
    const float u = first[d];
    const size_t base = (size_t)b * TT * DD + d;

    float kb[4], vb[4], rb[4];
#pragma unroll
    for (int j = 0; j < 4; j++) {
        kb[j] = k[base + (size_t)j * DD];
        vb[j] = v[base + (size_t)j * DD];
        rb[j] = r[base + (size_t)j * DD];
    }

    for (int t0 = 0; t0 < TT; t0 += 4) {
        float kn[4], vn[4], rn[4];
        if (t0 + 4 < TT) {
#pragma unroll
            for (int j = 0; j < 4; j++) {
                const size_t off = base + (size_t)(t0 + 4 + j) * DD;
                kn[j] = k[off]; vn[j] = v[off]; rn[j] = r[off];
            }
        } else {
#pragma unroll
            for (int j = 0; j < 4; j++) { kn[j] = 0.f; vn[j] = 0.f; rn[j] = 0.f; }
        }
#pragma unroll
        for (int j = 0; j < 4; j++) {
            const size_t off = base + (size_t)(t0 + j) * DD;
            const float kt = kb[j], vt = vb[j], rt = rb[j];
            float ww = u + kt;
            float p  = fmaxf(pp, ww);
            float e1 = expf(pp - p), e2 = expf(ww - p);
            float wkv = (e1 * aa + e2 * vt) / (e1 * bb + e2);
            rw[off] = rt * wkv;
            float ww2 = pp + w;
            float p2  = fmaxf(ww2, kt);
            float e1b = expf(ww2 - p2), e2b = expf(kt - p2);
            aa = e1b * aa + e2b * vt;
            bb = e1b * bb + e2b;
            pp = p2;
        }
#pragma unroll
        for (int j = 0; j < 4; j++) { kb[j] = kn[j]; vb[j] = vn[j]; rb[j] = rn[j]; }
    }
    aa_o[idx] = aa; bb_o[idx] = bb; pp_o[idx] = pp;
}

// ---------------- TF32 tensor-core GEMM: 128x128x16, mma.m16n8k8 ----------------
// 4 warps (128 threads), 64x64 warp tile (4 mt x 8 nt), 2-stage permuted smem.
// EPI: 0=none, 1=sigmoid, 2=relu^2, 3=acc+X, 4=X + S*acc

__device__ __forceinline__ unsigned f2tf32(float f) {
    unsigned u;
    asm("cvt.rna.tf32.f32 %0, %1;" : "=r"(u) : "f"(f));
    return u;
}

__device__ __forceinline__ void mma_tf32(
    float& c0, float& c1, float& c2, float& c3,
    unsigned a0, unsigned a1, unsigned a2, unsigned a3,
    unsigned b0, unsigned b1)
{
    asm volatile(
        "mma.sync.aligned.m16n8k8.row.col.f32.tf32.tf32.f32 "
        "{%0,%1,%2,%3}, {%4,%5,%6,%7}, {%8,%9}, {%0,%1,%2,%3};\n"
        : "+f"(c0), "+f"(c1), "+f"(c2), "+f"(c3)
        : "r"(a0), "r"(a1), "r"(a2), "r"(a3), "r"(b0), "r"(b1));
}

template<int EPI>
__global__ void __launch_bounds__(128, 2) tgemm(
    const float* __restrict__ A, const float* __restrict__ Bm, float* __restrict__ C,
    int M, int N, int K,
    const float* __restrict__ X, const float* __restrict__ S)
{
    // Two stages: stage word-offset = stage * 2048 (8 KB per side per stage).
    __shared__ __align__(16) unsigned As[4096];   // 16 KB
    __shared__ __align__(16) unsigned Bs[4096];   // 16 KB

    const int tid  = threadIdx.x;
    const int lane = tid & 31;
    const int warp = tid >> 5;      // 0..3
    const int wm   = warp >> 1;     // 0..1  (64-row half)
    const int wn   = warp & 1;      // 0..1  (64-col half)
    const int bm   = blockIdx.y * 128;
    const int bn   = blockIdx.x * 128;

    // ---- loader mapping ----
    // A: thread covers rows m = i*32 + ra (i=0..3), k-quad kqa.
    const int ra  = tid >> 2;           // 0..31
    const int kqa = (tid & 3) << 2;     // 0,4,8,12
    // offA(i) = offA0 + i*512   (derived: m&15 = ra&15, mt = i*2 + (ra>>4))
    const int rA   = ra & 15;
    const int ksA  = kqa >> 3;
    const int chA  = (kqa >> 2) & 1;
    const int regA = (rA >> 3) | (chA << 1);
    const int swzA = (regA << 2) ^ (ksA << 4);
    const int offA0 = ((((ra >> 4) << 1) | ksA) << 7) + (regA << 5)
                    + (((rA & 7) << 2) ^ swzA);
    // B: thread covers k-rows kB = i*4 + warp (i=0..3), n = lane*4+e.
    // offB(i,e) = (nt<<7) + i*32 + ls[e]
    const int ntL  = lane >> 1;
    const int swzL = ((ntL & 7) << 2) ^ ((ntL >> 3) << 1);
    int ls[4];
#pragma unroll
    for (int e = 0; e < 4; e++) {
        const int n = (lane << 2) + e;
        ls[e] = ((((n & 7) << 2) | (warp & 3)) ^ swzL);
    }
    const int offB0 = (ntL << 7);

    const float* Ap = A  + (size_t)(bm + ra) * K + kqa;
    const float* Bp = Bm + (size_t)warp * N + bn + (lane << 2);

    float acc[4][8][4];
#pragma unroll
    for (int i = 0; i < 4; i++)
#pragma unroll
        for (int j = 0; j < 8; j++)
#pragma unroll
            for (int e = 0; e < 4; e++) acc[i][j][e] = 0.f;

    float4 avr[4], bvr[4];
#pragma unroll
    for (int i = 0; i < 4; i++) {
        avr[i] = *(const float4*)(Ap + (size_t)(i * 32) * K);
        bvr[i] = *(const float4*)(Bp + (size_t)(i * 4) * N);
    }

    const int ns = K >> 4;
    for (int s = 0; s < ns; s++) {
        const int sb = (s & 1) << 11;     // stage word-offset 0 / 2048
        // ---- stage slab s (tf32-converted, fragment-permuted) ----
#pragma unroll
        for (int i = 0; i < 4; i++) {
            uint4 pa;
            pa.x = f2tf32(avr[i].x); pa.y = f2tf32(avr[i].y);
            pa.z = f2tf32(avr[i].z); pa.w = f2tf32(avr[i].w);
            *(uint4*)&As[sb + offA0 + i * 512] = pa;
            const int bb = sb + offB0 + i * 32;
            Bs[bb + ls[0]] = f2tf32(bvr[i].x);
            Bs[bb + ls[1]] = f2tf32(bvr[i].y);
            Bs[bb + ls[2]] = f2tf32(bvr[i].z);
            Bs[bb + ls[3]] = f2tf32(bvr[i].w);
        }
        __syncthreads();   // single barrier per slab (2-stage)

        // ---- prefetch next slab ----
        if (s + 1 < ns) {
            const int k1 = (s + 1) << 4;
#pragma unroll
            for (int i = 0; i < 4; i++) {
                avr[i] = *(const float4*)(Ap + (size_t)(i * 32) * K + k1);
                bvr[i] = *(const float4*)(Bp + (size_t)(k1 + i * 4) * N);
            }
        }

        // ---- compute: 2 k-steps, 4x8 m16n8 tiles per warp ----
        const unsigned* Asb = As + sb;
        const unsigned* Bsb = Bs + sb;
#pragma unroll
        for (int ks = 0; ks < 2; ks++) {
            unsigned af[4][4], bf[8][2];
#pragma unroll
            for (int mt = 0; mt < 4; mt++) {
                const int mtg = wm * 4 + mt;
                const int base = (((mtg << 1) | ks) << 7);
#pragma unroll
                for (int reg = 0; reg < 4; reg++)
                    af[mt][reg] = Asb[base + (reg << 5) + (lane ^ (reg << 2) ^ (ks << 4))];
            }
#pragma unroll
            for (int nt = 0; nt < 8; nt++) {
                const int ntg = wn * 8 + nt;
                const int swzB = (((ntg & 7) << 2)) ^ (((ntg >> 3) & 1) << 1);
                const int base = (((ntg << 1) | ks) << 6);
#pragma unroll
                for (int reg = 0; reg < 2; reg++)
                    bf[nt][reg] = Bsb[base + (reg << 5) + (lane ^ swzB)];
            }
#pragma unroll
            for (int mt = 0; mt < 4; mt++)
#pragma unroll
                for (int nt = 0; nt < 8; nt++)
                    mma_tf32(acc[mt][nt][0], acc[mt][nt][1], acc[mt][nt][2], acc[mt][nt][3],
                             af[mt][0], af[mt][1], af[mt][2], af[mt][3],
                             bf[nt][0], bf[nt][1]);
        }
        // no trailing barrier: next iteration writes the other stage
    }

    // ---- epilogue ----
    const int rbase = bm + wm * 64 + (lane >> 2);
    const int cbase = bn + wn * 64 + ((lane & 3) << 1);
#pragma unroll
    for (int mt = 0; mt < 4; mt++) {
#pragma unroll
        for (int h = 0; h < 2; h++) {
            const int row = rbase + mt * 16 + h * 8;
#pragma unroll
            for (int nt = 0; nt < 8; nt++) {
                const int col = cbase + nt * 8;
                const size_t idx = (size_t)row * N + col;
                float v0 = acc[mt][nt][h * 2 + 0];
                float v1 = acc[mt][nt][h * 2 + 1];
                if (EPI == 1) {
                    v0 = 1.f / (1.f + expf(-v0));
                    v1 = 1.f / (1.f + expf(-v1));
                } else if (EPI == 2) {
                    v0 = fmaxf(v0, 0.f); v0 *= v0;
                    v1 = fmaxf(v1, 0.f); v1 *= v1;
                } else if (EPI == 3) {
                    float2 xv = *(const float2*)&X[idx];
                    v0 += xv.x; v1 += xv.y;
                } else if (EPI == 4) {
                    float2 xv = *(const float2*)&X[idx];
                    float2 sv = *(const float2*)&S[idx];
                    v0 = xv.x + sv.x * v0;
                    v1 = xv.y + sv.y * v1;
                }
                float2 o; o.x = v0; o.y = v1;
                *(float2*)&C[idx] = o;
            }
        }
    }
}

// ---------------- host ----------------
extern "C" void kernel_launch(void* const* d_in, const int* in_sizes, int n_in,
                              void* d_out, int out_size)
{
    const float* x        = (const float*)d_in[0];
    const float* att_x    = (const float*)d_in[1];
    const float* att_a    = (const float*)d_in[2];
    const float* att_b    = (const float*)d_in[3];
    const float* att_p    = (const float*)d_in[4];
    const float* ffn_x    = (const float*)d_in[5];
    const float* ln1_g    = (const float*)d_in[6];
    const float* ln1_b    = (const float*)d_in[7];
    const float* ln2_g    = (const float*)d_in[8];
    const float* ln2_b    = (const float*)d_in[9];
    const float* tm_mix_k = (const float*)d_in[10];
    const float* tm_mix_v = (const float*)d_in[11];
    const float* tm_mix_r = (const float*)d_in[12];
    const float* tm_decay = (const float*)d_in[13];
    const float* tm_first = (const float*)d_in[14];
    const float* Wk       = (const float*)d_in[15];
    const float* Wv       = (const float*)d_in[16];
    const float* Wr       = (const float*)d_in[17];
    const float* Wo       = (const float*)d_in[18];
    const float* cm_mix_k = (const float*)d_in[19];
    const float* cm_mix_r = (const float*)d_in[20];
    const float* Ck       = (const float*)d_in[21];
    const float* Cr       = (const float*)d_in[22];
    const float* Cv       = (const float*)d_in[23];

    float* out = (float*)d_out;
    const size_t OFS_XN1 = (size_t)MM * DD;
    const size_t OFS_AA  = OFS_XN1 + (size_t)BB * DD;
    const size_t OFS_BB  = OFS_AA  + (size_t)BB * DD;
    const size_t OFS_PP  = OFS_BB  + (size_t)BB * DD;
    const size_t OFS_XN2 = OFS_PP  + (size_t)BB * DD;

    float *xn, *mk, *mv, *mr, *kk, *vv, *rr, *rw, *x1, *xn2, *mck, *mcr, *kc, *rc;
    cudaGetSymbolAddress((void**)&xn,  g_xn);
    cudaGetSymbolAddress((void**)&mk,  g_mk);
    cudaGetSymbolAddress((void**)&mv,  g_mv);
    cudaGetSymbolAddress((void**)&mr,  g_mr);
    cudaGetSymbolAddress((void**)&kk,  g_k);
    cudaGetSymbolAddress((void**)&vv,  g_v);
    cudaGetSymbolAddress((void**)&rr,  g_r);
    cudaGetSymbolAddress((void**)&rw,  g_rw);
    cudaGetSymbolAddress((void**)&x1,  g_x1);
    cudaGetSymbolAddress((void**)&xn2, g_xn2);
    cudaGetSymbolAddress((void**)&mck, g_mck);
    cudaGetSymbolAddress((void**)&mcr, g_mcr);
    cudaGetSymbolAddress((void**)&kc,  g_kc);
    cudaGetSymbolAddress((void**)&rc,  g_rc);

    const int mixBlocks = (MM * D4 + 255) / 256;

    // 1) ln1(x) -> xn  (+ xn_last output)
    ln_kernel<<<MM, 256>>>(x, ln1_g, ln1_b, xn, out + OFS_XN1);

    // 2) token shift + mix for k/v/r
    mix_kernel<3><<<mixBlocks, 256>>>(xn, att_x, tm_mix_k, tm_mix_v, tm_mix_r, mk, mv, mr);

    // 3) K, V, R GEMMs (R fused sigmoid)
    dim3 gD(DD / 128, MM / 128);
    tgemm<0><<<gD, 128>>>(mk, Wk, kk, MM, DD, DD, nullptr, nullptr);
    tgemm<0><<<gD, 128>>>(mv, Wv, vv, MM, DD, DD, nullptr, nullptr);
    tgemm<1><<<gD, 128>>>(mr, Wr, rr, MM, DD, DD, nullptr, nullptr);

    // 4) WKV scan (fused r*wkv), state outputs — 64-thread blocks on 128 CTAs
    wkv_kernel<<<(BB * DD) / 64, 64>>>(kk, vv, rr, att_a, att_b, att_p,
                                       tm_decay, tm_first, rw,
                                       out + OFS_AA, out + OFS_BB, out + OFS_PP);

    // 5) x1 = x + (r*wkv) @ Wo
    tgemm<3><<<gD, 128>>>(rw, Wo, x1, MM, DD, DD, x, nullptr);

    // 6) ln2(x1) -> xn2 (+ xn2_last output)
    ln_kernel<<<MM, 256>>>(x1, ln2_g, ln2_b, xn2, out + OFS_XN2);

    // 7) channel-mix token shift
    mix_kernel<2><<<mixBlocks, 256>>>(xn2, ffn_x, cm_mix_k, cm_mix_r, nullptr, mck, mcr, nullptr);

    // 8) kc = relu(mck @ Ck)^2   [M=8192, N=4096, K=1024]
    dim3 gF(FF / 128, MM / 128);
    tgemm<2><<<gF, 128>>>(mck, Ck, kc, MM, FF, DD, nullptr, nullptr);

    // 9) rc = sigmoid(mcr @ Cr)
    tgemm<1><<<gD, 128>>>(mcr, Cr, rc, MM, DD, DD, nullptr, nullptr);

    // 10) out = x1 + rc * (kc @ Cv)   [M=8192, N=1024, K=4096]
    tgemm<4><<<gD, 128>>>(kc, Cv, out, MM, DD, FF, x1, rc);
}

// round 11
// speedup vs baseline: 1.8872x; 1.5700x over previous
#include <cuda_runtime.h>
#include <cuda_fp16.h>
#include <cstdint>

#define BB 8
#define TT 1024
#define DD 1024
#define FF 4096
#define MM (BB*TT)          // 8192 rows
#define D4 (DD/4)

// ---------------- scratch (static device allocations; allowed) ----------------
__device__ float    g_xn [MM*DD];
__device__ unsigned g_mk [MM*DD/2];   // half2-packed GEMM A operands
__device__ unsigned g_mv [MM*DD/2];
__device__ unsigned g_mr [MM*DD/2];
__device__ float    g_k  [MM*DD];
__device__ float    g_v  [MM*DD];
__device__ float    g_r  [MM*DD];
__device__ __half   g_rw [MM*DD];     // r * wkv (half, GEMM A operand)
__device__ float    g_x1 [MM*DD];
__device__ float    g_xn2[MM*DD];
__device__ unsigned g_mck[MM*DD/2];
__device__ unsigned g_mcr[MM*DD/2];
__device__ __half   g_kc [MM*FF];     // relu^2 out (half, GEMM A operand)
__device__ float    g_rc [MM*DD];
// k-pair-packed fp16 weights: word(kh,n) = {h(W[2kh][n]), h(W[2kh+1][n])}
__device__ unsigned g_pWk[(DD/2)*DD];
__device__ unsigned g_pWv[(DD/2)*DD];
__device__ unsigned g_pWr[(DD/2)*DD];
__device__ unsigned g_pWo[(DD/2)*DD];
__device__ unsigned g_pCr[(DD/2)*DD];
__device__ unsigned g_pCk[(DD/2)*FF];
__device__ unsigned g_pCv[(FF/2)*DD];

// ---------------- weight pack: fp32 [Kd][Nd] -> half2 words [Kd/2][Nd] ----------------
__global__ void __launch_bounds__(256) pack_w(
    const float* __restrict__ in, unsigned* __restrict__ out, int Kd, int Nd)
{
    const int i = blockIdx.x * blockDim.x + threadIdx.x;
    const int tot = (Kd >> 1) * Nd;
    if (i >= tot) return;
    const int kh = i / Nd, n = i - kh * Nd;
    const float lo = in[(size_t)(2 * kh)     * Nd + n];
    const float hi = in[(size_t)(2 * kh + 1) * Nd + n];
    __half2 h = __floats2half2_rn(lo, hi);
    out[i] = *(unsigned*)&h;
}

// ---------------- LayerNorm ----------------
__global__ void __launch_bounds__(256) ln_kernel(
    const float* __restrict__ x, const float* __restrict__ g,
    const float* __restrict__ b, float* __restrict__ y,
    float* __restrict__ last)
{
    const int row = blockIdx.x;
    const float4* xr = (const float4*)(x + (size_t)row * DD);
    float4 v = xr[threadIdx.x];
    float s  = v.x + v.y + v.z + v.w;
    float ss = v.x*v.x + v.y*v.y + v.z*v.z + v.w*v.w;
#pragma unroll
    for (int o = 16; o; o >>= 1) {
        s  += __shfl_xor_sync(0xffffffffu, s,  o);
        ss += __shfl_xor_sync(0xffffffffu, ss, o);
    }
    __shared__ float sh[16];
    const int w = threadIdx.x >> 5, l = threadIdx.x & 31;
    if (l == 0) { sh[w] = s; sh[8 + w] = ss; }
    __syncthreads();
    s = 0.f; ss = 0.f;
#pragma unroll
    for (int i = 0; i < 8; i++) { s += sh[i]; ss += sh[8 + i]; }
    const float mean = s * (1.0f / DD);
    const float var  = ss * (1.0f / DD) - mean * mean;
    const float rstd = rsqrtf(var + 1e-3f);

    float4 gg = ((const float4*)g)[threadIdx.x];
    float4 bb = ((const float4*)b)[threadIdx.x];
    float4 o;
    o.x = (v.x - mean) * rstd * gg.x + bb.x;
    o.y = (v.y - mean) * rstd * gg.y + bb.y;
    o.z = (v.z - mean) * rstd * gg.z + bb.z;
    o.w = (v.w - mean) * rstd * gg.w + bb.w;
    ((float4*)(y + (size_t)row * DD))[threadIdx.x] = o;
    if (last && (row % TT) == (TT - 1)) {
        ((float4*)(last + (size_t)(row / TT) * DD))[threadIdx.x] = o;
    }
}

// ---------------- token-shift + lerp mixing -> half-packed outputs ----------------
template<int NOUT>
__global__ void __launch_bounds__(256) mix_kernel(
    const float* __restrict__ xn, const float* __restrict__ x0,
    const float* __restrict__ m0, const float* __restrict__ m1, const float* __restrict__ m2,
    unsigned* __restrict__ o0, unsigned* __restrict__ o1, unsigned* __restrict__ o2)
{
    const int i4 = blockIdx.x * blockDim.x + threadIdx.x;
    if (i4 >= MM * D4) return;
    const int d4 = i4 % D4;
    const int bt = i4 / D4;
    const int t = bt % TT, b = bt / TT;
    float4 xc = ((const float4*)xn)[i4];
    float4 xp = (t == 0) ? ((const float4*)x0)[b * D4 + d4]
                         : ((const float4*)xn)[i4 - D4];
    {
        float4 m = ((const float4*)m0)[d4];
        __half2 p0 = __floats2half2_rn(xp.x + (xc.x - xp.x) * m.x, xp.y + (xc.y - xp.y) * m.y);
        __half2 p1 = __floats2half2_rn(xp.z + (xc.z - xp.z) * m.z, xp.w + (xc.w - xp.w) * m.w);
        uint2 wv; wv.x = *(unsigned*)&p0; wv.y = *(unsigned*)&p1;
        ((uint2*)o0)[i4] = wv;
    }
    if (NOUT >= 2) {
        float4 m = ((const float4*)m1)[d4];
        __half2 p0 = __floats2half2_rn(xp.x + (xc.x - xp.x) * m.x, xp.y + (xc.y - xp.y) * m.y);
        __half2 p1 = __floats2half2_rn(xp.z + (xc.z - xp.z) * m.z, xp.w + (xc.w - xp.w) * m.w);
        uint2 wv; wv.x = *(unsigned*)&p0; wv.y = *(unsigned*)&p1;
        ((uint2*)o1)[i4] = wv;
    }
    if (NOUT >= 3) {
        float4 m = ((const float4*)m2)[d4];
        __half2 p0 = __floats2half2_rn(xp.x + (xc.x - xp.x) * m.x, xp.y + (xc.y - xp.y) * m.y);
        __half2 p1 = __floats2half2_rn(xp.z + (xc.z - xp.z) * m.z, xp.w + (xc.w - xp.w) * m.w);
        uint2 wv; wv.x = *(unsigned*)&p0; wv.y = *(unsigned*)&p1;
        ((uint2*)o2)[i4] = wv;
    }
}

// ---------------- WKV scan: 4-deep prefetch, 64-thread blocks, half rw out ----------------
__global__ void __launch_bounds__(64) wkv_kernel(
    const float* __restrict__ k, const float* __restrict__ v, const float* __restrict__ r,
    const float* __restrict__ a0, const float* __restrict__ b0, const float* __restrict__ p0,
    const float* __restrict__ decay, const float* __restrict__ first,
    __half* __restrict__ rw,
    float* __restrict__ aa_o, float* __restrict__ bb_o, float* __restrict__ pp_o)
{
    const int idx = blockIdx.x * blockDim.x + threadIdx.x;
    if (idx >= BB * DD) return;
    const int d = idx % DD, b = idx / DD;
    float aa = a0[idx], bb = b0[idx], pp = p0[idx];
    const float w = -expf(decay[d]);
    const float u = first[d];
    const size_t base = (size_t)b * TT * DD + d;

    float kb[4], vb[4], rb[4];
#pragma unroll
    for (int j = 0; j < 4; j++) {
        kb[j] = k[base + (size_t)j * DD];
        vb[j] = v[base + (size_t)j * DD];
        rb[j] = r[base + (size_t)j * DD];
    }

    for (int t0 = 0; t0 < TT; t0 += 4) {
        float kn[4], vn[4], rn[4];
        if (t0 + 4 < TT) {
#pragma unroll
            for (int j = 0; j < 4; j++) {
                const size_t off = base + (size_t)(t0 + 4 + j) * DD;
                kn[j] = k[off]; vn[j] = v[off]; rn[j] = r[off];
            }
        } else {
#pragma unroll
            for (int j = 0; j < 4; j++) { kn[j] = 0.f; vn[j] = 0.f; rn[j] = 0.f; }
        }
#pragma unroll
        for (int j = 0; j < 4; j++) {
            const size_t off = base + (size_t)(t0 + j) * DD;
            const float kt = kb[j], vt = vb[j], rt = rb[j];
            float ww = u + kt;
            float p  = fmaxf(pp, ww);
            float e1 = expf(pp - p), e2 = expf(ww - p);
            float wkv = (e1 * aa + e2 * vt) / (e1 * bb + e2);
            rw[off] = __float2half_rn(rt * wkv);
            float ww2 = pp + w;
            float p2  = fmaxf(ww2, kt);
            float e1b = expf(ww2 - p2), e2b = expf(kt - p2);
            aa = e1b * aa + e2b * vt;
            bb = e1b * bb + e2b;
            pp = p2;
        }
#pragma unroll
        for (int j = 0; j < 4; j++) { kb[j] = kn[j]; vb[j] = vn[j]; rb[j] = rn[j]; }
    }
    aa_o[idx] = aa; bb_o[idx] = bb; pp_o[idx] = pp;
}

// ---------------- fp16 tensor-core GEMM: 128x128x16, mma.m16n8k16, cp.async 3-stage ----------------
// A: half-pair words [M][K/2]; B: packed half-pair words [K/2][N]; C fp32 (EPI=2: half).
// smem: A rows stride 12 words (8 data + 4 pad); B rows stride 136 words (128 + 8 pad).
// Conflict-free linear addressing on both LDGSTS-store and LDS-load sides.
// EPI: 0=none, 1=sigmoid, 2=relu^2->half, 3=acc+X, 4=X + S*acc

#define CP16(d, s)  asm volatile("cp.async.cg.shared.global [%0], [%1], 16;\n" :: "r"(d), "l"(s) : "memory")
#define CPCOMMIT()  asm volatile("cp.async.commit_group;\n" ::: "memory")
#define CPWAIT1()   asm volatile("cp.async.wait_group 1;\n" ::: "memory")
#define CPWAIT0()   asm volatile("cp.async.wait_group 0;\n" ::: "memory")

__device__ __forceinline__ void mma16816(float* c, const unsigned* a, const unsigned* b) {
    asm volatile(
        "mma.sync.aligned.m16n8k16.row.col.f32.f16.f16.f32 "
        "{%0,%1,%2,%3}, {%4,%5,%6,%7}, {%8,%9}, {%0,%1,%2,%3};\n"
        : "+f"(c[0]), "+f"(c[1]), "+f"(c[2]), "+f"(c[3])
        : "r"(a[0]), "r"(a[1]), "r"(a[2]), "r"(a[3]), "r"(b[0]), "r"(b[1]));
}

#define A_STRIDE 12            // words per A smem row
#define B_STRIDE 136           // words per B smem row
#define A_STAGE_W (128 * A_STRIDE)   // 1536 words
#define B_STAGE_W (8 * B_STRIDE)     // 1088 words

template<int EPI>
__global__ void __launch_bounds__(128, 2) tgemm(
    const unsigned* __restrict__ A32, const unsigned* __restrict__ B32, void* __restrict__ Cp,
    int M, int N, int K,
    const float* __restrict__ X, const float* __restrict__ S)
{
    __shared__ __align__(16) unsigned sA[3 * A_STAGE_W];
    __shared__ __align__(16) unsigned sB[3 * B_STAGE_W];

    const int tid  = threadIdx.x;
    const int lane = tid & 31;
    const int warp = tid >> 5;      // 0..3
    const int wm   = warp >> 1;     // 0..1
    const int wn   = warp & 1;      // 0..1
    const int bm   = blockIdx.y * 128;
    const int bn   = blockIdx.x * 128;
    const int Kw   = K >> 1;

    const uint32_t aB = (uint32_t)__cvta_generic_to_shared(sA);
    const uint32_t bB = (uint32_t)__cvta_generic_to_shared(sB);

    // producer per-thread constants
    const unsigned* aRow = A32 + (size_t)(bm + tid) * Kw;       // A row m = tid
    const uint32_t  aD   = aB + tid * (A_STRIDE * 4);
    const int bkh = tid >> 4;                                   // B smem row 0..7
    const int bc  = tid & 15;                                   // chunk base
    const unsigned* bRow = B32 + bn + (size_t)bkh * N;
    const uint32_t  bD   = bB + bkh * (B_STRIDE * 4);

    auto issue = [&](int s, int st) {
        const int k0w = s << 3;                                 // (s*16)/2
        const unsigned* as = aRow + k0w;
        uint32_t ad = aD + st * (A_STAGE_W * 4);
        CP16(ad,      as);
        CP16(ad + 16, as + 4);
        const unsigned* bs = bRow + (size_t)k0w * N;
        uint32_t bd = bD + st * (B_STAGE_W * 4);
        CP16(bd + bc * 16,        bs + bc * 4);
        CP16(bd + (bc + 16) * 16, bs + (bc + 16) * 4);
        CPCOMMIT();
    };

    float acc[4][8][4];
#pragma unroll
    for (int i = 0; i < 4; i++)
#pragma unroll
        for (int j = 0; j < 8; j++)
#pragma unroll
            for (int e = 0; e < 4; e++) acc[i][j][e] = 0.f;

    // compute-side per-thread bases (purely linear addressing)
    const int aT = wm * 768 + (lane >> 2) * A_STRIDE + (lane & 3);
    const int bT = (lane & 3) * B_STRIDE + wn * 64 + (lane >> 2);

    const int ns = K >> 4;
    issue(0, 0); issue(1, 1);
    int st = 0, st2 = 2;
    for (int s = 0; s < ns; s++) {
        if (s == ns - 1) { CPWAIT0(); } else { CPWAIT1(); }
        __syncthreads();
        if (s + 2 < ns) { issue(s + 2, st2); st2 = (st2 == 2) ? 0 : st2 + 1; }

        const unsigned* Aw = sA + st * A_STAGE_W;
        const unsigned* Bw = sB + st * B_STAGE_W;
        unsigned af[4][4], bf[8][2];
#pragma unroll
        for (int mt = 0; mt < 4; mt++)
#pragma unroll
            for (int r = 0; r < 4; r++)
                af[mt][r] = Aw[aT + mt * 192 + (r & 1) * 96 + (r >> 1) * 4];
#pragma unroll
        for (int nt = 0; nt < 8; nt++)
#pragma unroll
            for (int r = 0; r < 2; r++)
                bf[nt][r] = Bw[bT + nt * 8 + r * (4 * B_STRIDE)];
#pragma unroll
        for (int mt = 0; mt < 4; mt++)
#pragma unroll
            for (int nt = 0; nt < 8; nt++)
                mma16816(acc[mt][nt], af[mt], bf[nt]);

        st = (st == 2) ? 0 : st + 1;
    }

    // ---- epilogue ----
    float* C = (float*)Cp;
    const int rbase = bm + wm * 64 + (lane >> 2);
    const int cbase = bn + wn * 64 + ((lane & 3) << 1);
#pragma unroll
    for (int mt = 0; mt < 4; mt++) {
#pragma unroll
        for (int h = 0; h < 2; h++) {
            const int row = rbase + mt * 16 + h * 8;
#pragma unroll
            for (int nt = 0; nt < 8; nt++) {
                const int col = cbase + nt * 8;
                const size_t idx = (size_t)row * N + col;
                float v0 = acc[mt][nt][h * 2 + 0];
                float v1 = acc[mt][nt][h * 2 + 1];
                if (EPI == 1) {
                    v0 = 1.f / (1.f + expf(-v0));
                    v1 = 1.f / (1.f + expf(-v1));
                    float2 o; o.x = v0; o.y = v1;
                    *(float2*)&C[idx] = o;
                } else if (EPI == 2) {
                    v0 = fmaxf(v0, 0.f); v0 *= v0;
                    v1 = fmaxf(v1, 0.f); v1 *= v1;
                    __half2 hh = __floats2half2_rn(v0, v1);
                    ((unsigned*)Cp)[idx >> 1] = *(unsigned*)&hh;
                } else if (EPI == 3) {
                    float2 xv = *(const float2*)&X[idx];
                    float2 o; o.x = v0 + xv.x; o.y = v1 + xv.y;
                    *(float2*)&C[idx] = o;
                } else if (EPI == 4) {
                    float2 xv = *(const float2*)&X[idx];
                    float2 sv = *(const float2*)&S[idx];
                    float2 o;
                    o.x = xv.x + sv.x * v0;
                    o.y = xv.y + sv.y * v1;
                    *(float2*)&C[idx] = o;
                } else {
                    float2 o; o.x = v0; o.y = v1;
                    *(float2*)&C[idx] = o;
                }
            }
        }
    }
}

// ---------------- host ----------------
extern "C" void kernel_launch(void* const* d_in, const int* in_sizes, int n_in,
                              void* d_out, int out_size)
{
    const float* x        = (const float*)d_in[0];
    const float* att_x    = (const float*)d_in[1];
    const float* att_a    = (const float*)d_in[2];
    const float* att_b    = (const float*)d_in[3];
    const float* att_p    = (const float*)d_in[4];
    const float* ffn_x    = (const float*)d_in[5];
    const float* ln1_g    = (const float*)d_in[6];
    const float* ln1_b    = (const float*)d_in[7];
    const float* ln2_g    = (const float*)d_in[8];
    const float* ln2_b    = (const float*)d_in[9];
    const float* tm_mix_k = (const float*)d_in[10];
    const float* tm_mix_v = (const float*)d_in[11];
    const float* tm_mix_r = (const float*)d_in[12];
    const float* tm_decay = (const float*)d_in[13];
    const float* tm_first = (const float*)d_in[14];
    const float* Wk       = (const float*)d_in[15];
    const float* Wv       = (const float*)d_in[16];
    const float* Wr       = (const float*)d_in[17];
    const float* Wo       = (const float*)d_in[18];
    const float* cm_mix_k = (const float*)d_in[19];
    const float* cm_mix_r = (const float*)d_in[20];
    const float* Ck       = (const float*)d_in[21];
    const float* Cr       = (const float*)d_in[22];
    const float* Cv       = (const float*)d_in[23];

    float* out = (float*)d_out;
    const size_t OFS_XN1 = (size_t)MM * DD;
    const size_t OFS_AA  = OFS_XN1 + (size_t)BB * DD;
    const size_t OFS_BB  = OFS_AA  + (size_t)BB * DD;
    const size_t OFS_PP  = OFS_BB  + (size_t)BB * DD;
    const size_t OFS_XN2 = OFS_PP  + (size_t)BB * DD;

    float *xn, *kk, *vv, *rr, *x1, *xn2, *rc;
    unsigned *mk, *mv, *mr, *mck, *mcr;
    __half *rw, *kc;
    unsigned *pWk, *pWv, *pWr, *pWo, *pCr, *pCk, *pCv;
    cudaGetSymbolAddress((void**)&xn,  g_xn);
    cudaGetSymbolAddress((void**)&mk,  g_mk);
    cudaGetSymbolAddress((void**)&mv,  g_mv);
    cudaGetSymbolAddress((void**)&mr,  g_mr);
    cudaGetSymbolAddress((void**)&kk,  g_k);
    cudaGetSymbolAddress((void**)&vv,  g_v);
    cudaGetSymbolAddress((void**)&rr,  g_r);
    cudaGetSymbolAddress((void**)&rw,  g_rw);
    cudaGetSymbolAddress((void**)&x1,  g_x1);
    cudaGetSymbolAddress((void**)&xn2, g_xn2);
    cudaGetSymbolAddress((void**)&mck, g_mck);
    cudaGetSymbolAddress((void**)&mcr, g_mcr);
    cudaGetSymbolAddress((void**)&kc,  g_kc);
    cudaGetSymbolAddress((void**)&rc,  g_rc);
    cudaGetSymbolAddress((void**)&pWk, g_pWk);
    cudaGetSymbolAddress((void**)&pWv, g_pWv);
    cudaGetSymbolAddress((void**)&pWr, g_pWr);
    cudaGetSymbolAddress((void**)&pWo, g_pWo);
    cudaGetSymbolAddress((void**)&pCr, g_pCr);
    cudaGetSymbolAddress((void**)&pCk, g_pCk);
    cudaGetSymbolAddress((void**)&pCv, g_pCv);

    const int mixBlocks = (MM * D4 + 255) / 256;

    // 0) pack weights to fp16 k-pair layout
    const int pwD = ((DD / 2) * DD + 255) / 256;
    pack_w<<<pwD, 256>>>(Wk, pWk, DD, DD);
    pack_w<<<pwD, 256>>>(Wv, pWv, DD, DD);
    pack_w<<<pwD, 256>>>(Wr, pWr, DD, DD);
    pack_w<<<pwD, 256>>>(Wo, pWo, DD, DD);
    pack_w<<<pwD, 256>>>(Cr, pCr, DD, DD);
    pack_w<<<((DD / 2) * FF + 255) / 256, 256>>>(Ck, pCk, DD, FF);
    pack_w<<<((FF / 2) * DD + 255) / 256, 256>>>(Cv, pCv, FF, DD);

    // 1) ln1(x) -> xn  (+ xn_last output)
    ln_kernel<<<MM, 256>>>(x, ln1_g, ln1_b, xn, out + OFS_XN1);

    // 2) token shift + mix for k/v/r (half-packed outputs)
    mix_kernel<3><<<mixBlocks, 256>>>(xn, att_x, tm_mix_k, tm_mix_v, tm_mix_r, mk, mv, mr);

    // 3) K, V, R GEMMs (R fused sigmoid)
    dim3 gD(DD / 128, MM / 128);
    tgemm<0><<<gD, 128>>>(mk, pWk, kk, MM, DD, DD, nullptr, nullptr);
    tgemm<0><<<gD, 128>>>(mv, pWv, vv, MM, DD, DD, nullptr, nullptr);
    tgemm<1><<<gD, 128>>>(mr, pWr, rr, MM, DD, DD, nullptr, nullptr);

    // 4) WKV scan (fused r*wkv -> half), state outputs
    wkv_kernel<<<(BB * DD) / 64, 64>>>(kk, vv, rr, att_a, att_b, att_p,
                                       tm_decay, tm_first, rw,
                                       out + OFS_AA, out + OFS_BB, out + OFS_PP);

    // 5) x1 = x + (r*wkv) @ Wo
    tgemm<3><<<gD, 128>>>((const unsigned*)rw, pWo, x1, MM, DD, DD, x, nullptr);

    // 6) ln2(x1) -> xn2 (+ xn2_last output)
    ln_kernel<<<MM, 256>>>(x1, ln2_g, ln2_b, xn2, out + OFS_XN2);

    // 7) channel-mix token shift (half-packed outputs)
    mix_kernel<2><<<mixBlocks, 256>>>(xn2, ffn_x, cm_mix_k, cm_mix_r, nullptr, mck, mcr, nullptr);

    // 8) kc = relu(mck @ Ck)^2 -> half   [M=8192, N=4096, K=1024]
    dim3 gF(FF / 128, MM / 128);
    tgemm<2><<<gF, 128>>>(mck, pCk, kc, MM, FF, DD, nullptr, nullptr);

    // 9) rc = sigmoid(mcr @ Cr)
    tgemm<1><<<gD, 128>>>(mcr, pCr, rc, MM, DD, DD, nullptr, nullptr);

    // 10) out = x1 + rc * (kc @ Cv)   [M=8192, N=1024, K=4096]
    tgemm<4><<<gD, 128>>>((const unsigned*)kc, pCv, out, MM, DD, FF, x1, rc);
}